// round 12
// baseline (speedup 1.0000x reference)
#include <cuda_runtime.h>
#include <cuda_bf16.h>
#include <cstdint>
#include <math.h>

// Problem constants
#define BQ   4
#define CH   256
#define HW   4096
#define VT   (BQ*HW)          // 16384 vertices
#define NP   2048             // past samples
#define NCLS 4
#define TEMP_INV 10.0f
#define EPS  1e-8f

// GEMM tiling: grid = 256. CTA = (m-block = bx>>1, n-half = bx&1).
// Each CTA: 128 rows x 1024 cols (8 n-tiles of 128), K=256 fp8 resident.
#define GM 128
#define GN 128
#define NHT 8                 // n-tiles per CTA

// SMEM: fp8 rows 256B + 16B pad = 272B (17 chunks, odd -> conflict-free)
#define ASTRIDE  272
#define TILE_SZ  (GM*ASTRIDE)            // 34816
#define OFF_A    0
#define OFF_B0   TILE_SZ
#define OFF_CLSB (3*TILE_SZ)             // 104448 (int[2048] = 8KB)
#define OFF_CLSA (OFF_CLSB + 8192)       // int[128]
#define OFF_RED  (OFF_CLSA + 512)
#define SMEM_TOTAL (OFF_RED + 1024)      // 114176 (~111.5KB) -> 2 CTAs/SM

// Scratch (allocation-free)
__device__ __align__(256) uint8_t g_Xf8[VT*CH];   // normalized X e4m3 [v][d]
__device__ __align__(256) uint8_t g_Pf8[NP*CH];   // normalized P e4m3 [n][d]
__device__ __align__(256) int   g_clsV[VT];
__device__ __align__(256) int   g_clsP[NP];
__device__ __align__(256) float g_sameG[VT];
__device__ __align__(256) float g_otherG[VT];
__device__ int      g_doneM[VT/GM];      // per-m-block arrival counters
__device__ int      g_cnt[NCLS];
__device__ float    g_sum;
__device__ unsigned g_done;

__device__ __forceinline__ uint32_t smem_u32(const void* p) {
    uint32_t a;
    asm("{ .reg .u64 t; cvta.to.shared.u64 t, %1; cvt.u32.u64 %0, t; }" : "=r"(a) : "l"(p));
    return a;
}
__device__ __forceinline__ void ldsm_x4(uint32_t addr, uint32_t& r0, uint32_t& r1,
                                        uint32_t& r2, uint32_t& r3) {
    asm volatile("ldmatrix.sync.aligned.m8n8.x4.shared.b16 {%0,%1,%2,%3}, [%4];"
                 : "=r"(r0), "=r"(r1), "=r"(r2), "=r"(r3) : "r"(addr));
}
__device__ __forceinline__ void mma_fp8(float* c, const uint32_t* a, const uint32_t* b) {
    asm volatile(
        "mma.sync.aligned.m16n8k32.row.col.f32.e4m3.e4m3.f32 "
        "{%0,%1,%2,%3}, {%4,%5,%6,%7}, {%8,%9}, {%0,%1,%2,%3};"
        : "+f"(c[0]), "+f"(c[1]), "+f"(c[2]), "+f"(c[3])
        : "r"(a[0]), "r"(a[1]), "r"(a[2]), "r"(a[3]), "r"(b[0]), "r"(b[1]));
}
__device__ __forceinline__ uint16_t pack_e4m3x2(float lo, float hi) {
    uint16_t h;
    asm("cvt.rn.satfinite.e4m3x2.f32 %0, %1, %2;" : "=h"(h) : "f"(hi), "f"(lo));
    return h;
}
#define CP16(dst, src) \
    asm volatile("cp.async.cg.shared.global [%0], [%1], 16;" :: "r"(dst), "l"(src))
#define CP_COMMIT() asm volatile("cp.async.commit_group;" ::: "memory")
#define CP_WAIT(n)  asm volatile("cp.async.wait_group %0;" :: "n"(n) : "memory")

// ---------------------------------------------------------------------------
// Kernel 1: single pass over X -> inverse norm, class, e4m3 transpose.
// Also zeroes all per-launch state (graph-replay safe).
// ---------------------------------------------------------------------------
__global__ __launch_bounds__(256) void prep_x_fused(const float* __restrict__ X,
                                                    const float* __restrict__ Y) {
    __shared__ float sx[32][257];
    __shared__ float sInv[32];
    int t  = threadIdx.x;
    int b  = blockIdx.y;
    int v0 = blockIdx.x * 32;
    int rowBase = b * HW + v0;

    if (blockIdx.x == 0 && b == 0) {
        if (t < NCLS) g_cnt[t] = 0;
        if (t == 4)  g_sum = 0.0f;
        if (t == 5)  g_done = 0u;
        if (t >= 64 && t < 64 + VT / GM) g_doneM[t - 64] = 0;
    }
    if (t < 32) {               // zero this block's 32 rows of the combine buffers
        g_sameG[rowBase + t]  = 0.0f;
        g_otherG[rowBase + t] = 0.0f;
    }

    const float* xb = X + (size_t)b * CH * HW + v0;
#pragma unroll
    for (int i = 0; i < 32; i++) {
        int c = i * 8 + (t >> 5);
        int v = t & 31;
        sx[v][c] = xb[(size_t)c * HW + v];
    }
    __syncthreads();

    {
        int v = t >> 3, part = t & 7;
        float acc = 0.0f;
#pragma unroll
        for (int j = 0; j < 32; j++) {
            float x = sx[v][part + 8 * j];
            acc = fmaf(x, x, acc);
        }
#pragma unroll
        for (int o = 4; o; o >>= 1) acc += __shfl_xor_sync(0xffffffffu, acc, o);
        if (part == 0) {
            sInv[v] = 1.0f / fmaxf(sqrtf(acc), EPS);
            const float* yb = Y + (size_t)b * NCLS * HW + v0 + v;
            float best = yb[0]; int bc = 0;
#pragma unroll
            for (int k = 1; k < NCLS; k++) {
                float val = yb[(size_t)k * HW];
                if (val > best) { best = val; bc = k; }
            }
            g_clsV[rowBase + v] = bc;
        }
    }
    __syncthreads();

    // write normalized e4m3, vertex-major: 8 channels (uint2) per item
    uint2* out = (uint2*)g_Xf8 + (size_t)rowBase * 32;
#pragma unroll
    for (int i = 0; i < 4; i++) {
        int idx = t + i * 256;          // 0..1023
        int v = idx >> 5, g = idx & 31;
        float inv = sInv[v];
        const float* row = &sx[v][g * 8];
        uint16_t h0 = pack_e4m3x2(row[0] * inv, row[1] * inv);
        uint16_t h1 = pack_e4m3x2(row[2] * inv, row[3] * inv);
        uint16_t h2 = pack_e4m3x2(row[4] * inv, row[5] * inv);
        uint16_t h3 = pack_e4m3x2(row[6] * inv, row[7] * inv);
        uint2 val;
        val.x = (uint32_t)h0 | ((uint32_t)h1 << 16);
        val.y = (uint32_t)h2 | ((uint32_t)h3 << 16);
        out[(size_t)v * 32 + g] = val;
    }
}

// ---------------------------------------------------------------------------
// Kernel 2: normalize past samples -> e4m3, class + counts
// ---------------------------------------------------------------------------
__global__ void prep_p(const float* __restrict__ P,
                       const float* __restrict__ L) {
    int gwarp = (blockIdx.x * blockDim.x + threadIdx.x) >> 5;
    int lane  = threadIdx.x & 31;
    if (gwarp >= NP) return;
    const float4* p = (const float4*)(P + (size_t)gwarp * CH) + lane * 2;
    float4 u = p[0], w = p[1];      // 8 consecutive floats
    float acc = u.x*u.x + u.y*u.y + u.z*u.z + u.w*u.w
              + w.x*w.x + w.y*w.y + w.z*w.z + w.w*w.w;
#pragma unroll
    for (int o = 16; o; o >>= 1) acc += __shfl_xor_sync(0xffffffffu, acc, o);
    float inv = 1.0f / fmaxf(sqrtf(acc), EPS);
    uint16_t h0 = pack_e4m3x2(u.x * inv, u.y * inv);
    uint16_t h1 = pack_e4m3x2(u.z * inv, u.w * inv);
    uint16_t h2 = pack_e4m3x2(w.x * inv, w.y * inv);
    uint16_t h3 = pack_e4m3x2(w.z * inv, w.w * inv);
    uint2 val;
    val.x = (uint32_t)h0 | ((uint32_t)h1 << 16);
    val.y = (uint32_t)h2 | ((uint32_t)h3 << 16);
    ((uint2*)g_Pf8)[(size_t)gwarp * 32 + lane] = val;
    if (lane == 0) {
        const float* l = L + gwarp * NCLS;
        float best = l[0]; int bc = 0;
#pragma unroll
        for (int k = 1; k < NCLS; k++) if (l[k] > best) { best = l[k]; bc = k; }
        g_clsP[gwarp] = bc;
        atomicAdd(&g_cnt[bc], 1);
    }
}

// ---------------------------------------------------------------------------
// Kernel 3: FP8 HMMA GEMM, grid=256 (2 CTAs/SM), 512 threads.
// CTA = (m-block, n-half). Warp tile 32x32, warp grid 4x4, k-step 32 (fp8).
// Fragment layouts are byte-identical to the bf16 m16n8k16 path.
// ---------------------------------------------------------------------------
__global__ __launch_bounds__(512) void gemm_fp8(float* __restrict__ outp) {
    extern __shared__ __align__(16) char smem[];
    uint32_t sb = smem_u32(smem);
    int tid  = threadIdx.x;
    int wid  = tid >> 5;
    int lane = tid & 31;
    int mblk = blockIdx.x >> 1;
    int nh   = blockIdx.x & 1;
    int m0   = mblk * GM;
    int nt0  = nh * NHT;

    // ---- prologue: cp.async A + class tables + B stages 0,1
    const uint4* Ag = (const uint4*)(g_Xf8 + (size_t)m0 * CH);
#pragma unroll
    for (int i = 0; i < 4; i++) {
        int idx = tid + i * 512;          // 0..2047
        int row = idx >> 4, chunk = idx & 15;
        CP16(sb + OFF_A + (row * 17 + chunk) * 16, Ag + idx);
    }
    CP16(sb + OFF_CLSB + tid * 16, ((const uint4*)g_clsP) + tid);
    if (tid < 32)
        CP16(sb + OFF_CLSA + tid * 16, ((const uint4*)(g_clsV + m0)) + tid);
    {
        const uint4* Bg = (const uint4*)(g_Pf8 + (size_t)nt0 * GN * CH);
#pragma unroll
        for (int i = 0; i < 4; i++) {
            int idx = tid + i * 512;
            int row = idx >> 4, chunk = idx & 15;
            CP16(sb + OFF_B0 + (row * 17 + chunk) * 16, Bg + idx);
        }
    }
    CP_COMMIT();
    {
        const uint4* Bg = (const uint4*)(g_Pf8 + (size_t)(nt0 + 1) * GN * CH);
#pragma unroll
        for (int i = 0; i < 4; i++) {
            int idx = tid + i * 512;
            int row = idx >> 4, chunk = idx & 15;
            CP16(sb + OFF_B0 + TILE_SZ + (row * 17 + chunk) * 16, Bg + idx);
        }
    }
    CP_COMMIT();

    int wm0 = (wid >> 2) * 32;
    int wn0 = (wid & 3) * 32;

    uint32_t aBase = sb + OFF_A + (uint32_t)(wm0 + (lane & 15)) * ASTRIDE + (lane >> 4) * 16;
    uint32_t bOff  = (uint32_t)(wn0 + (lane & 15)) * ASTRIDE + (lane >> 4) * 16;

    const int* sClsA = (const int*)(smem + OFF_CLSA);
    const int* sClsB = (const int*)(smem + OFF_CLSB);

    float sAa[2], oAa[2], sBa[2], oBa[2];
#pragma unroll
    for (int mi = 0; mi < 2; mi++) { sAa[mi] = oAa[mi] = sBa[mi] = oBa[mi] = 0.0f; }

    int colBase = wn0 + (lane & 3) * 2;

    for (int t = 0; t < NHT; t++) {
        if (t < NHT - 1) CP_WAIT(1); else CP_WAIT(0);
        __syncthreads();

        uint32_t bBase = sb + OFF_B0 + (uint32_t)(t & 1) * TILE_SZ + bOff;

        float acc[2][4][4];
#pragma unroll
        for (int mi = 0; mi < 2; mi++)
#pragma unroll
            for (int ni = 0; ni < 4; ni++)
#pragma unroll
                for (int r = 0; r < 4; r++) acc[mi][ni][r] = 0.0f;

        // K=256 fp8 -> 8 k-steps of 32 bytes
#pragma unroll
        for (int ks = 0; ks < 8; ks++) {
            uint32_t a[2][4], b[4][2];
#pragma unroll
            for (int mi = 0; mi < 2; mi++)
                ldsm_x4(aBase + mi * 16 * ASTRIDE + ks * 32,
                        a[mi][0], a[mi][1], a[mi][2], a[mi][3]);
#pragma unroll
            for (int nj = 0; nj < 2; nj++) {
                uint32_t t0, t1, t2, t3;
                ldsm_x4(bBase + nj * 16 * ASTRIDE + ks * 32, t0, t1, t2, t3);
                b[nj * 2 + 0][0] = t0; b[nj * 2 + 0][1] = t2;
                b[nj * 2 + 1][0] = t1; b[nj * 2 + 1][1] = t3;
            }
#pragma unroll
            for (int mi = 0; mi < 2; mi++)
#pragma unroll
                for (int ni = 0; ni < 4; ni++)
                    mma_fp8(acc[mi][ni], a[mi], b[ni]);
        }

        int nGlob = (nt0 + t) * GN;
#pragma unroll
        for (int mi = 0; mi < 2; mi++) {
            int rA = wm0 + mi * 16 + (lane >> 2);
            int cvA = sClsA[rA];
            int cvB = sClsA[rA + 8];
#pragma unroll
            for (int ni = 0; ni < 4; ni++) {
                int c0 = nGlob + colBase + ni * 8;
                int cls0 = sClsB[(c0 & 2047)], cls1 = sClsB[((c0 + 1) & 2047)];
                float e0 = __expf((acc[mi][ni][0] - 1.0f) * TEMP_INV);
                float e1 = __expf((acc[mi][ni][1] - 1.0f) * TEMP_INV);
                float e2 = __expf((acc[mi][ni][2] - 1.0f) * TEMP_INV);
                float e3 = __expf((acc[mi][ni][3] - 1.0f) * TEMP_INV);
                if (cls0 == cvA) sAa[mi] += e0; else oAa[mi] += e0;
                if (cls1 == cvA) sAa[mi] += e1; else oAa[mi] += e1;
                if (cls0 == cvB) sBa[mi] += e2; else oBa[mi] += e2;
                if (cls1 == cvB) sBa[mi] += e3; else oBa[mi] += e3;
            }
        }

        __syncthreads();
        if (t + 2 < NHT) {
            const uint4* Bg = (const uint4*)(g_Pf8 + (size_t)(nt0 + t + 2) * GN * CH);
            uint32_t dst = sb + OFF_B0 + (uint32_t)(t & 1) * TILE_SZ;
#pragma unroll
            for (int i = 0; i < 4; i++) {
                int idx = tid + i * 512;
                int row = idx >> 4, chunk = idx & 15;
                CP16(dst + (row * 17 + chunk) * 16, Bg + idx);
            }
        }
        CP_COMMIT();
    }

    // ---- combine within CTA
    float* sS = (float*)(smem + OFF_RED);
    float* sO = sS + 128;
    if (tid < 128) { sS[tid] = 0.0f; sO[tid] = 0.0f; }
    __syncthreads();
#pragma unroll
    for (int mi = 0; mi < 2; mi++) {
        float sA = sAa[mi], oA = oAa[mi], sB = sBa[mi], oB = oBa[mi];
#pragma unroll
        for (int off = 1; off <= 2; off <<= 1) {
            sA += __shfl_xor_sync(0xffffffffu, sA, off);
            oA += __shfl_xor_sync(0xffffffffu, oA, off);
            sB += __shfl_xor_sync(0xffffffffu, sB, off);
            oB += __shfl_xor_sync(0xffffffffu, oB, off);
        }
        if ((lane & 3) == 0) {
            int rA = wm0 + mi * 16 + (lane >> 2);
            atomicAdd(&sS[rA], sA);
            atomicAdd(&sO[rA], oA);
            atomicAdd(&sS[rA + 8], sB);
            atomicAdd(&sO[rA + 8], oB);
        }
    }
    __syncthreads();

    // ---- cross-CTA combine (2 CTAs per m-block share rows)
    if (tid < 128) {
        atomicAdd(&g_sameG[m0 + tid], sS[tid]);
        atomicAdd(&g_otherG[m0 + tid], sO[tid]);
    }
    __threadfence();
    __shared__ int sFlag;
    if (tid == 0) {
        int old = atomicAdd(&g_doneM[mblk], 1);
        sFlag = (old == 1);
    }
    __syncthreads();

    if (sFlag) {   // second CTA for this m-block: finish the 128 rows
        __shared__ float wsum[4];
        if (tid < 128) {
            float cnt = (float)g_cnt[sClsA[tid]];
            // read combined sums via L2 (atomics bypass L1; read L2-coherent)
            float sm = ((float)NP - cnt) + __ldcg(&g_sameG[m0 + tid]);
            float ot = cnt + __ldcg(&g_otherG[m0 + tid]);
            float r = sm / ot;
#pragma unroll
            for (int off = 16; off; off >>= 1) r += __shfl_xor_sync(0xffffffffu, r, off);
            if (lane == 0) wsum[wid] = r;
        }
        __syncthreads();
        if (tid == 0) {
            atomicAdd(&g_sum, wsum[0] + wsum[1] + wsum[2] + wsum[3]);
            __threadfence();
            unsigned d = atomicAdd(&g_done, 1u);
            if (d == (unsigned)(VT / GM - 1)) {
                outp[0] = g_sum / (float)VT;
            }
        }
    }
}

// ---------------------------------------------------------------------------
extern "C" void kernel_launch(void* const* d_in, const int* in_sizes, int n_in,
                              void* d_out, int out_size) {
    const float* X = (const float*)d_in[0];   // (4,256,64,64)
    const float* Y = (const float*)d_in[1];   // (4,4,64,64)
    const float* P = (const float*)d_in[2];   // (2048,256)
    const float* L = (const float*)d_in[3];   // (2048,4)
    float* out = (float*)d_out;

    cudaFuncSetAttribute(gemm_fp8, cudaFuncAttributeMaxDynamicSharedMemorySize, SMEM_TOTAL);

    prep_x_fused<<<dim3(HW / 32, BQ), 256>>>(X, Y);
    prep_p<<<(NP * 32) / 256, 256>>>(P, L);
    gemm_fp8<<<2 * (VT / GM), 512, SMEM_TOTAL>>>(out);
}

// round 15
// speedup vs baseline: 1.0650x; 1.0650x over previous
#include <cuda_runtime.h>
#include <cuda_bf16.h>
#include <cstdint>
#include <math.h>

// Problem constants
#define BQ   4
#define CH   256
#define HW   4096
#define VT   16384
#define NP   2048
#define NCLS 4
#define TEMP_INV 10.0f
#define EPS  1e-8f

// GEMM: grid=128 CTAs, one per 128-row m-block. 512 threads, 16 warps.
// Warp grid 2(m) x 8(n), warp tile 64x32, CTA superstep = 256 cols x 128 K.
// 16 supersteps = 8 n-chunks x 2 k-halves.
#define GM 128
#define NSS 16

#define ASTR 528      // A row: 256 bf16 = 512B + 16 pad (33 chunks, odd)
#define BSTR 272      // B row: 128 bf16 = 256B + 16 pad (17 chunks, odd)
#define OFF_A    0                 // 128*528  = 67584
#define OFF_B0   67584             // 256*272  = 69632
#define OFF_B1   137216            // also A-prep staging (33024B < 69632)
#define OFF_CLSB 206848            // int[2048] = 8192
#define OFF_CLSA 215040            // int[128]
#define OFF_INV  215552            // float[128]
#define OFF_RED  216064            // float[256] (sumsq during prep, sS/sO at end)
#define SMEM_TOTAL 217088          // ~212KB dynamic

// Scratch (allocation-free)
__device__ __align__(256) __nv_bfloat16 g_Pbf[NP*CH];
__device__ __align__(256) int g_clsP[NP];
__device__ float    g_sum;
__device__ unsigned g_done;

__device__ __forceinline__ uint32_t smem_u32(const void* p) {
    uint32_t a;
    asm("{ .reg .u64 t; cvta.to.shared.u64 t, %1; cvt.u32.u64 %0, t; }" : "=r"(a) : "l"(p));
    return a;
}
__device__ __forceinline__ void ldsm_x4(uint32_t addr, uint32_t& r0, uint32_t& r1,
                                        uint32_t& r2, uint32_t& r3) {
    asm volatile("ldmatrix.sync.aligned.m8n8.x4.shared.b16 {%0,%1,%2,%3}, [%4];"
                 : "=r"(r0), "=r"(r1), "=r"(r2), "=r"(r3) : "r"(addr));
}
__device__ __forceinline__ void mma_bf16(float* c, const uint32_t* a, const uint32_t* b) {
    asm volatile(
        "mma.sync.aligned.m16n8k16.row.col.f32.bf16.bf16.f32 "
        "{%0,%1,%2,%3}, {%4,%5,%6,%7}, {%8,%9}, {%0,%1,%2,%3};"
        : "+f"(c[0]), "+f"(c[1]), "+f"(c[2]), "+f"(c[3])
        : "r"(a[0]), "r"(a[1]), "r"(a[2]), "r"(a[3]), "r"(b[0]), "r"(b[1]));
}
#define CP16(dst, src) \
    asm volatile("cp.async.cg.shared.global [%0], [%1], 16;" :: "r"(dst), "l"(src))
#define CP_COMMIT() asm volatile("cp.async.commit_group;" ::: "memory")
#define CP_WAIT(n)  asm volatile("cp.async.wait_group %0;" :: "n"(n) : "memory")

// ---------------------------------------------------------------------------
// Kernel 1: normalize past samples -> bf16, class labels; zero g_sum/g_done.
// ---------------------------------------------------------------------------
__global__ void prep_p(const float* __restrict__ P,
                       const float* __restrict__ L) {
    if (blockIdx.x == 0) {
        if (threadIdx.x == 0) g_sum = 0.0f;
        if (threadIdx.x == 1) g_done = 0u;
    }
    int gwarp = (blockIdx.x * blockDim.x + threadIdx.x) >> 5;
    int lane  = threadIdx.x & 31;
    if (gwarp >= NP) return;
    const float4* p = (const float4*)(P + (size_t)gwarp * CH) + lane * 2;
    float4 u = p[0], w = p[1];
    float acc = u.x*u.x + u.y*u.y + u.z*u.z + u.w*u.w
              + w.x*w.x + w.y*w.y + w.z*w.z + w.w*w.w;
#pragma unroll
    for (int o = 16; o; o >>= 1) acc += __shfl_xor_sync(0xffffffffu, acc, o);
    float inv = 1.0f / fmaxf(sqrtf(acc), EPS);
    __nv_bfloat162 p0 = __floats2bfloat162_rn(u.x * inv, u.y * inv);
    __nv_bfloat162 p1 = __floats2bfloat162_rn(u.z * inv, u.w * inv);
    __nv_bfloat162 p2 = __floats2bfloat162_rn(w.x * inv, w.y * inv);
    __nv_bfloat162 p3 = __floats2bfloat162_rn(w.z * inv, w.w * inv);
    uint4 val;
    val.x = *(uint32_t*)&p0; val.y = *(uint32_t*)&p1;
    val.z = *(uint32_t*)&p2; val.w = *(uint32_t*)&p3;
    ((uint4*)g_Pbf)[(size_t)gwarp * 32 + lane] = val;
    if (lane == 0) {
        const float* l = L + gwarp * NCLS;
        float best = l[0]; int bc = 0;
#pragma unroll
        for (int k = 1; k < NCLS; k++) if (l[k] > best) { best = l[k]; bc = k; }
        g_clsP[gwarp] = bc;
    }
}

// ---------------------------------------------------------------------------
// Kernel 2: fully fused — in-CTA X prep (norm folded into epilogue) +
// persistent-A bf16 HMMA GEMM (64x32 warp tiles) + exp/bucket + finalize.
// ---------------------------------------------------------------------------
__global__ __launch_bounds__(512, 1) void gemm_fused(const float* __restrict__ X,
                                                     const float* __restrict__ Y,
                                                     float* __restrict__ outp) {
    extern __shared__ __align__(1024) char smem[];
    uint32_t sb = smem_u32(smem);
    int tid  = threadIdx.x;
    int wid  = tid >> 5;
    int lane = tid & 31;
    int m0   = blockIdx.x * GM;
    int b    = m0 >> 12;
    int hw0  = m0 & (HW - 1);

    float* stag  = (float*)(smem + OFF_B1);    // staging (overlaps B1; B1 loads later)
    float* sSS   = (float*)(smem + OFF_RED);   // sumsq during prep
    float* sInv  = (float*)(smem + OFF_INV);
    int*   sClsA = (int*)(smem + OFF_CLSA);
    int*   sClsB = (int*)(smem + OFF_CLSB);

    // ---- group0: B stage 0 (nc=0, kh=0) + class table
#pragma unroll
    for (int i = 0; i < 8; i++) {
        int idx = tid + i * 512;              // 0..4095
        int r = idx >> 4, ch = idx & 15;
        CP16(sb + OFF_B0 + r * BSTR + ch * 16,
             (const char*)g_Pbf + (size_t)r * 512 + ch * 16);
    }
    CP16(sb + OFF_CLSB + tid * 16, (const char*)g_clsP + tid * 16);
    CP_COMMIT();

    // ---- in-CTA A prep: 4 chunks of 64 channels, staged fp32 in B1 region.
    if (tid < 128) sSS[tid] = 0.0f;
    __syncthreads();
    const float* Xs = X + (size_t)b * CH * HW + hw0;
#pragma unroll
    for (int cc = 0; cc < 4; cc++) {
        int c0 = cc * 64;
#pragma unroll
        for (int i = 0; i < 16; i++) {
            int idx = tid + i * 512;          // 0..8191
            int v = idx & 127, c = idx >> 7;  // c 0..63
            stag[c * 129 + v] = Xs[(size_t)(c0 + c) * HW + v];
        }
        __syncthreads();
        {
            int v = tid & 127, part = tid >> 7;   // 4 partials per vertex
            float a = 0.0f;
#pragma unroll
            for (int j = 0; j < 16; j++) {
                float x = stag[(part * 16 + j) * 129 + v];
                a = fmaf(x, x, a);
            }
            atomicAdd(&sSS[v], a);
            // write UNNORMALIZED bf16 A (norm folded into epilogue)
#pragma unroll
            for (int j = 0; j < 8; j++) {
                int c = part * 16 + 2 * j;
                __nv_bfloat162 pk = __floats2bfloat162_rn(stag[c * 129 + v],
                                                          stag[(c + 1) * 129 + v]);
                *(uint32_t*)(smem + OFF_A + v * ASTR + (c0 + c) * 2) = *(uint32_t*)&pk;
            }
        }
        __syncthreads();
    }
    if (tid < 128) {
        sInv[tid] = 1.0f / fmaxf(sqrtf(sSS[tid]), EPS);
        const float* yb = Y + (size_t)b * NCLS * HW + hw0 + tid;
        float best = yb[0]; int bc = 0;
#pragma unroll
        for (int k = 1; k < NCLS; k++) {
            float v = yb[(size_t)k * HW];
            if (v > best) { best = v; bc = k; }
        }
        sClsA[tid] = bc;
    }
    // ---- group1: B stage 1 (nc=0, kh=1) into B1 (staging done)
#pragma unroll
    for (int i = 0; i < 8; i++) {
        int idx = tid + i * 512;
        int r = idx >> 4, ch = idx & 15;
        CP16(sb + OFF_B1 + r * BSTR + ch * 16,
             (const char*)g_Pbf + (size_t)r * 512 + 256 + ch * 16);
    }
    CP_COMMIT();
    __syncthreads();

    // ---- mainloop
    int wm0 = (wid >> 3) * 64;                // m half
    int wn0 = (wid & 7) * 32;                 // n slot within 256-col chunk
    uint32_t aBase = sb + OFF_A + (uint32_t)(wm0 + (lane & 15)) * ASTR + (lane >> 4) * 16;
    uint32_t bOff  = (uint32_t)(wn0 + (lane & 15)) * BSTR + (lane >> 4) * 16;
    int colBase = (lane & 3) * 2;

    float sAa[4], oAa[4], sBa[4], oBa[4];
#pragma unroll
    for (int mi = 0; mi < 4; mi++) { sAa[mi] = oAa[mi] = sBa[mi] = oBa[mi] = 0.0f; }

    float acc[4][4][4];

    for (int s = 0; s < NSS; s++) {
        int kh = s & 1, nc = s >> 1;
        if (s < NSS - 1) CP_WAIT(1); else CP_WAIT(0);
        __syncthreads();

        uint32_t bBase = sb + (kh ? OFF_B1 : OFF_B0) + bOff;

        if (kh == 0) {
#pragma unroll
            for (int mi = 0; mi < 4; mi++)
#pragma unroll
                for (int ni = 0; ni < 4; ni++)
#pragma unroll
                    for (int r = 0; r < 4; r++) acc[mi][ni][r] = 0.0f;
        }

#pragma unroll
        for (int ks = 0; ks < 8; ks++) {
            uint32_t a[4][4], bb[4][2];
#pragma unroll
            for (int mi = 0; mi < 4; mi++)
                ldsm_x4(aBase + mi * 16 * ASTR + kh * 256 + ks * 32,
                        a[mi][0], a[mi][1], a[mi][2], a[mi][3]);
#pragma unroll
            for (int nj = 0; nj < 2; nj++) {
                uint32_t t0, t1, t2, t3;
                ldsm_x4(bBase + nj * 16 * BSTR + ks * 32, t0, t1, t2, t3);
                bb[nj * 2 + 0][0] = t0; bb[nj * 2 + 0][1] = t2;
                bb[nj * 2 + 1][0] = t1; bb[nj * 2 + 1][1] = t3;
            }
#pragma unroll
            for (int mi = 0; mi < 4; mi++)
#pragma unroll
                for (int ni = 0; ni < 4; ni++)
                    mma_bf16(acc[mi][ni], a[mi], bb[ni]);
        }

        if (kh == 1) {
            int nGlob = nc * 256 + wn0;
#pragma unroll
            for (int mi = 0; mi < 4; mi++) {
                int rA = wm0 + mi * 16 + (lane >> 2);
                int rB = rA + 8;
                int cvA = sClsA[rA], cvB = sClsA[rB];
                float iA = sInv[rA], iB = sInv[rB];
#pragma unroll
                for (int ni = 0; ni < 4; ni++) {
                    int c0 = nGlob + colBase + ni * 8;
                    int cls0 = sClsB[c0], cls1 = sClsB[c0 + 1];
                    float e0 = __expf((acc[mi][ni][0] * iA - 1.0f) * TEMP_INV);
                    float e1 = __expf((acc[mi][ni][1] * iA - 1.0f) * TEMP_INV);
                    float e2 = __expf((acc[mi][ni][2] * iB - 1.0f) * TEMP_INV);
                    float e3 = __expf((acc[mi][ni][3] * iB - 1.0f) * TEMP_INV);
                    if (cls0 == cvA) sAa[mi] += e0; else oAa[mi] += e0;
                    if (cls1 == cvA) sAa[mi] += e1; else oAa[mi] += e1;
                    if (cls0 == cvB) sBa[mi] += e2; else oBa[mi] += e2;
                    if (cls1 == cvB) sBa[mi] += e3; else oBa[mi] += e3;
                }
            }
        }

        __syncthreads();     // buffer (s&1) free before reissue
        if (s + 2 < NSS) {
            int nc2 = (s + 2) >> 1;
            uint32_t dst = sb + ((s & 1) ? OFF_B1 : OFF_B0);
#pragma unroll
            for (int i = 0; i < 8; i++) {
                int idx = tid + i * 512;
                int r = idx >> 4, ch = idx & 15;
                CP16(dst + r * BSTR + ch * 16,
                     (const char*)g_Pbf + ((size_t)nc2 * 256 + r) * 512 + (s & 1) * 256 + ch * 16);
            }
        }
        CP_COMMIT();
    }

    // ---- finalize: class counts from smem table, bucket combine, ratio, mean
    float* sS = (float*)(smem + OFF_RED);
    float* sO = sS + 128;
    __shared__ int   sCnt[NCLS];
    __shared__ float wsum[4];
    if (tid < 128) { sS[tid] = 0.0f; sO[tid] = 0.0f; }
    if (tid < NCLS) sCnt[tid] = 0;
    __syncthreads();
    {
        int t0 = 0, t1 = 0, t2 = 0, t3 = 0;
#pragma unroll
        for (int i = 0; i < 4; i++) {
            int c = sClsB[tid + i * 512];
            t0 += (c == 0); t1 += (c == 1); t2 += (c == 2); t3 += (c == 3);
        }
#pragma unroll
        for (int o = 16; o; o >>= 1) {
            t0 += __shfl_xor_sync(0xffffffffu, t0, o);
            t1 += __shfl_xor_sync(0xffffffffu, t1, o);
            t2 += __shfl_xor_sync(0xffffffffu, t2, o);
            t3 += __shfl_xor_sync(0xffffffffu, t3, o);
        }
        if (lane == 0) {
            atomicAdd(&sCnt[0], t0); atomicAdd(&sCnt[1], t1);
            atomicAdd(&sCnt[2], t2); atomicAdd(&sCnt[3], t3);
        }
    }
#pragma unroll
    for (int mi = 0; mi < 4; mi++) {
        float sA = sAa[mi], oA = oAa[mi], sB = sBa[mi], oB = oBa[mi];
#pragma unroll
        for (int off = 1; off <= 2; off <<= 1) {
            sA += __shfl_xor_sync(0xffffffffu, sA, off);
            oA += __shfl_xor_sync(0xffffffffu, oA, off);
            sB += __shfl_xor_sync(0xffffffffu, sB, off);
            oB += __shfl_xor_sync(0xffffffffu, oB, off);
        }
        if ((lane & 3) == 0) {
            int rA = wm0 + mi * 16 + (lane >> 2);
            atomicAdd(&sS[rA], sA);
            atomicAdd(&sO[rA], oA);
            atomicAdd(&sS[rA + 8], sB);
            atomicAdd(&sO[rA + 8], oB);
        }
    }
    __syncthreads();

    if (tid < 128) {
        float cnt = (float)sCnt[sClsA[tid]];
        float r = (((float)NP - cnt) + sS[tid]) / (cnt + sO[tid]);
#pragma unroll
        for (int off = 16; off; off >>= 1) r += __shfl_xor_sync(0xffffffffu, r, off);
        if (lane == 0) wsum[wid] = r;
    }
    __syncthreads();
    if (tid == 0) {
        atomicAdd(&g_sum, wsum[0] + wsum[1] + wsum[2] + wsum[3]);
        __threadfence();
        unsigned d = atomicAdd(&g_done, 1u);
        if (d == (unsigned)(gridDim.x - 1)) {
            outp[0] = g_sum / (float)VT;
        }
    }
}

// ---------------------------------------------------------------------------
extern "C" void kernel_launch(void* const* d_in, const int* in_sizes, int n_in,
                              void* d_out, int out_size) {
    const float* X = (const float*)d_in[0];   // (4,256,64,64)
    const float* Y = (const float*)d_in[1];   // (4,4,64,64)
    const float* P = (const float*)d_in[2];   // (2048,256)
    const float* L = (const float*)d_in[3];   // (2048,4)
    float* out = (float*)d_out;

    cudaFuncSetAttribute(gemm_fused, cudaFuncAttributeMaxDynamicSharedMemorySize, SMEM_TOTAL);

    prep_p<<<(NP * 32) / 256, 256>>>(P, L);
    gemm_fused<<<VT / GM, 512, SMEM_TOTAL>>>(X, Y, out);
}